// round 4
// baseline (speedup 1.0000x reference)
#include <cuda_runtime.h>
#include <math.h>
#include <stdint.h>

#define CC   512
#define NN1  8192
#define NN2  131072
#define NTOT 139265
#define EE   1000000
#define KK1  820
#define KK2  3280
#define MM   4101
#define CHUNK 64
#define MAXWORK 8192

// output layout (float32, tuple concatenated)
#define OFF_XPOOL 0ULL
#define OFF_A     2099712ULL
#define OFF_BATCH 18917913ULL
#define OFF_CLUST 18922014ULL
#define OFF_NNT   19061279ULL
#define OFF_NTREE 19065380ULL
#define OFF_FIT   19069481ULL
#define OFF_NEWXY 19208746ULL

// ---------------- device scratch ----------------
__device__ float g_f1[NN1];
__device__ float g_f2[NN2];
__device__ int   g_rank[NN1];
__device__ float g_thr[KK1 * 3];
__device__ int   g_cluster1[NN1];
__device__ int   g_parents[NN2];
__device__ int   g_counts1[KK1];
__device__ int   g_starts1[KK1];
__device__ int   g_offs1[KK1];
__device__ int   g_gmembers[NN2];
__device__ int   g_cand_idx[KK1 * 4];
__device__ float g_cand_xyf[KK1 * 4 * 3];
__device__ int   g_cluster[NTOT];
__device__ int   g_countsM[MM];
__device__ int   g_startsM[MM];
__device__ int   g_chunkStart[MM + 1];
__device__ int   g_offsM[MM];
__device__ int   g_cmembers[NTOT];
__device__ unsigned g_work[MAXWORK];
__device__ float g_partial[MAXWORK * CC];     // 16 MB chunk partial sums
__device__ float g_pxy[MAXWORK * 2];
__device__ int   g_workCount;
__device__ int   g_ctr_rank, g_ctr_par, g_ctr_c2;
__device__ int   g_minTree;
__device__ float g_norm1, g_norm2;

__device__ __forceinline__ unsigned int f2ord(float f) {
    unsigned int u = __float_as_uint(f);
    return (u & 0x80000000u) ? ~u : (u | 0x80000000u);
}

// exclusive scan of n<=256*PER ints by one 256-thread block
template <int PER>
__device__ void block_scan_excl(const int* __restrict__ in, int* __restrict__ out, int n,
                                int* total) {
    __shared__ int sh[256];
    int t = threadIdx.x;
    int base = t * PER;
    int loc[PER];
    int s = 0;
#pragma unroll
    for (int i = 0; i < PER; i++) {
        int v = (base + i < n) ? in[base + i] : 0;
        loc[i] = s; s += v;
    }
    sh[t] = s;
    __syncthreads();
    for (int off = 1; off < 256; off <<= 1) {
        int a = (t >= off) ? sh[t - off] : 0;
        __syncthreads();
        sh[t] += a;
        __syncthreads();
    }
    int prev = (t > 0) ? sh[t - 1] : 0;
#pragma unroll
    for (int i = 0; i < PER; i++)
        if (base + i < n) out[base + i] = prev + loc[i];
    if (total && t == 255) *total = sh[255];
    __syncthreads();
}

// ---------------- setup
__global__ void setup_kernel(const float* __restrict__ w1, const float* __restrict__ w2) {
    int i = blockIdx.x * blockDim.x + threadIdx.x;  // 8192 threads
    if (i < NN1) g_rank[i] = 0;
    if (i < KK1) { g_counts1[i] = 0; g_offs1[i] = 0; }
    if (i < MM)  { g_countsM[i] = (i == 0) ? 1 : 0; g_offsM[i] = 0; }
    if (i == 0)  {
        g_minTree = 0x7fffffff; g_cluster[0] = 0;
        g_workCount = 0; g_ctr_rank = 0; g_ctr_par = 0; g_ctr_c2 = 0;
    }
    if (blockIdx.x == 0) {
        __shared__ float s1[256], s2[256];
        int t = threadIdx.x;
        float a = w1[t], b = w1[t + 256];
        float c = w2[t], d = w2[t + 256];
        s1[t] = a * a + b * b;
        s2[t] = c * c + d * d;
        __syncthreads();
        for (int off = 128; off; off >>= 1) {
            if (t < off) { s1[t] += s1[t + off]; s2[t] += s2[t + off]; }
            __syncthreads();
        }
        if (t == 0) { g_norm1 = sqrtf(s1[0]); g_norm2 = sqrtf(s2[0]); }
    }
}

// one warp per row: f = tanh(dot(x_row, w)/||w||); blocks 0..63 also do tree-min
__global__ void f_kernel(const float* __restrict__ x,
                         const float* __restrict__ w1,
                         const float* __restrict__ w2,
                         const int* __restrict__ tree) {
    if (blockIdx.x < 64) {
        __shared__ int smin[256];
        int v = 0x7fffffff;
        for (int i = blockIdx.x * 256 + threadIdx.x; i < NN2; i += 64 * 256)
            v = min(v, tree[1 + NN1 + i]);
        smin[threadIdx.x] = v;
        __syncthreads();
        for (int off = 128; off; off >>= 1) {
            if (threadIdx.x < off) smin[threadIdx.x] = min(smin[threadIdx.x], smin[threadIdx.x + off]);
            __syncthreads();
        }
        if (threadIdx.x == 0) atomicMin(&g_minTree, smin[0]);
        __syncthreads();
    }
    int gw = (blockIdx.x * blockDim.x + threadIdx.x) >> 5;
    int lane = threadIdx.x & 31;
    if (gw >= NN1 + NN2) return;
    const float4* xr = (const float4*)(x + (size_t)(1 + gw) * CC);
    const float4* wr = (const float4*)((gw < NN1) ? w1 : w2);
    float s = 0.f;
#pragma unroll
    for (int k = 0; k < 4; k++) {
        float4 a = xr[lane + 32 * k];
        float4 b = wr[lane + 32 * k];
        s += a.x * b.x; s += a.y * b.y; s += a.z * b.z; s += a.w * b.w;
    }
    for (int off = 16; off; off >>= 1) s += __shfl_xor_sync(0xffffffffu, s, off);
    if (lane == 0) {
        float nrm = (gw < NN1) ? g_norm1 : g_norm2;
        float f = tanhf(s / nrm);
        if (gw < NN1) g_f1[gw] = f; else g_f2[gw - NN1] = f;
    }
}

// brute-force stable rank of f1; last block writes thresholds
__global__ void rank_kernel(const float* __restrict__ xy) {
    __shared__ unsigned long long sk[1024];
    int jbase = (blockIdx.x & 7) * 1024;
    int i = (blockIdx.x >> 3) * 256 + threadIdx.x;
    for (int k = threadIdx.x; k < 1024; k += 256) {
        int j = jbase + k;
        sk[k] = ((unsigned long long)f2ord(g_f1[j]) << 32) | (unsigned)j;
    }
    __syncthreads();
    unsigned long long ki = ((unsigned long long)f2ord(g_f1[i]) << 32) | (unsigned)i;
    int c = 0;
#pragma unroll 8
    for (int k = 0; k < 1024; k++) c += (sk[k] < ki) ? 1 : 0;
    atomicAdd(&g_rank[i], c);
    __shared__ bool isLast;
    __threadfence();
    if (threadIdx.x == 0) isLast = (atomicAdd(&g_ctr_rank, 1) == gridDim.x - 1);
    __syncthreads();
    if (isLast) {
        for (int ii = threadIdx.x; ii < NN1; ii += 256) {
            int r = g_rank[ii];
            if (r % 10 == 0) {
                int s = r / 10;
                g_thr[s * 3 + 0] = xy[(size_t)(1 + ii) * 2];
                g_thr[s * 3 + 1] = xy[(size_t)(1 + ii) * 2 + 1];
                g_thr[s * 3 + 2] = g_f1[ii];
            }
        }
    }
}

// cluster_1: warp per node, lexicographic (d, t) first-min; fused countsM
__global__ void cluster1_kernel(const float* __restrict__ xy) {
    __shared__ float sx[KK1], sy[KK1], sf[KK1];
    for (int k = threadIdx.x; k < KK1; k += blockDim.x) {
        sx[k] = g_thr[k * 3 + 0];
        sy[k] = g_thr[k * 3 + 1];
        sf[k] = g_thr[k * 3 + 2];
    }
    __syncthreads();
    int node = blockIdx.x * 8 + (threadIdx.x >> 5);
    int lane = threadIdx.x & 31;
    if (node >= NN1) return;
    float xj = xy[(size_t)(1 + node) * 2];
    float yj = xy[(size_t)(1 + node) * 2 + 1];
    float fj = g_f1[node];
    float best = INFINITY;
    int bt = KK1;
    for (int t = lane; t < KK1; t += 32) {
        float dx = sx[t] - xj, dy = sy[t] - yj;
        float d = sqrtf(dx * dx + dy * dy) + fabsf(sf[t] - fj);
        if (d < best) { best = d; bt = t; }
    }
    for (int off = 16; off; off >>= 1) {
        float ob = __shfl_xor_sync(0xffffffffu, best, off);
        int   ot = __shfl_xor_sync(0xffffffffu, bt, off);
        if (ob < best || (ob == best && ot < bt)) { best = ob; bt = ot; }
    }
    if (lane == 0) {
        g_cluster1[node] = bt;
        g_cluster[1 + node] = bt + 1;
        atomicAdd(&g_countsM[bt + 1], 1);
    }
}

// parents + group counts; last block does scan0
__global__ void parents_kernel(const int* __restrict__ tree) {
    int i = blockIdx.x * blockDim.x + threadIdx.x;
    if (i < NN2) {
        int p = g_cluster1[tree[1 + NN1 + i] - g_minTree];
        g_parents[i] = p;
        atomicAdd(&g_counts1[p], 1);
    }
    __shared__ bool isLast;
    __threadfence();
    if (threadIdx.x == 0) isLast = (atomicAdd(&g_ctr_par, 1) == gridDim.x - 1);
    __syncthreads();
    if (isLast) block_scan_excl<4>(g_counts1, g_starts1, KK1, nullptr);
}

__global__ void scatter1_kernel() {
    int i = blockIdx.x * blockDim.x + threadIdx.x;
    if (i >= NN2) return;
    int p = g_parents[i];
    int pos = g_starts1[p] + atomicAdd(&g_offs1[p], 1);
    g_gmembers[pos] = i;
}

// warp-per-group top-4 smallest (comp_key, idx); stable
__global__ void top4_kernel(const float* __restrict__ xy) {
    int g = (blockIdx.x * blockDim.x + threadIdx.x) >> 5;
    int lane = threadIdx.x & 31;
    if (g >= KK1) return;
    int start = g_starts1[g], cnt = g_counts1[g];
    const unsigned long long SENT = 0xFFFFFFFFFFFFFFFFull;
    unsigned long long best[4] = {SENT, SENT, SENT, SENT};
    float p4 = 4.0f * (float)g;
    for (int k = lane; k < cnt; k += 32) {
        int i = g_gmembers[start + k];
        float key = p4 + g_f2[i];
        unsigned long long v = ((unsigned long long)f2ord(key) << 32) | (unsigned)i;
        if (v < best[3]) {
            if (v < best[0]) { best[3]=best[2]; best[2]=best[1]; best[1]=best[0]; best[0]=v; }
            else if (v < best[1]) { best[3]=best[2]; best[2]=best[1]; best[1]=v; }
            else if (v < best[2]) { best[3]=best[2]; best[2]=v; }
            else best[3]=v;
        }
    }
    int ptr = 0;
    for (int r = 0; r < 4; r++) {
        unsigned long long v = (ptr < 4) ? best[ptr] : SENT;
        unsigned long long m = v;
        for (int off = 16; off; off >>= 1) {
            unsigned long long o = __shfl_xor_sync(0xffffffffu, m, off);
            if (o < m) m = o;
        }
        unsigned ball = __ballot_sync(0xffffffffu, (ptr < 4) && (v == m));
        if (ball) { int src = __ffs(ball) - 1; if (lane == src) ptr++; }
        if (lane == 0) {
            bool valid = (m != SENT);
            int idx = valid ? (int)(unsigned)(m & 0xffffffffULL) : -1;
            g_cand_idx[g * 4 + r] = idx;
            if (valid) {
                g_cand_xyf[(g * 4 + r) * 3 + 0] = xy[(size_t)(1 + NN1 + idx) * 2];
                g_cand_xyf[(g * 4 + r) * 3 + 1] = xy[(size_t)(1 + NN1 + idx) * 2 + 1];
                g_cand_xyf[(g * 4 + r) * 3 + 2] = g_f2[idx];
            }
        }
    }
}

// cluster_2 + countsM; last block does scanM + chunk scan
__global__ void cluster2_kernel(const float* __restrict__ xy) {
    int i = blockIdx.x * blockDim.x + threadIdx.x;
    if (i < NN2) {
        int p = g_parents[i];
        float xi = xy[(size_t)(1 + NN1 + i) * 2];
        float yi = xy[(size_t)(1 + NN1 + i) * 2 + 1];
        float fi = g_f2[i];
        float best = INFINITY;
        int loc = 0;
#pragma unroll
        for (int r = 0; r < 4; r++) {
            int ci = g_cand_idx[p * 4 + r];
            if (ci >= 0) {
                float ax = g_cand_xyf[(p * 4 + r) * 3 + 0];
                float ay = g_cand_xyf[(p * 4 + r) * 3 + 1];
                float af = g_cand_xyf[(p * 4 + r) * 3 + 2];
                float dx = ax - xi, dy = ay - yi;
                float d = sqrtf(dx * dx + dy * dy) + fabsf(af - fi);
                if (d < best) { best = d; loc = r; }
            }
        }
        int c = p * 4 + loc + 1 + KK1;
        g_cluster[1 + NN1 + i] = c;
        atomicAdd(&g_countsM[c], 1);
    }
    __shared__ bool isLast;
    __threadfence();
    if (threadIdx.x == 0) isLast = (atomicAdd(&g_ctr_c2, 1) == gridDim.x - 1);
    __syncthreads();
    if (isLast) {
        block_scan_excl<17>(g_countsM, g_startsM, MM, nullptr);
        // chunk-count scan: nch[m] = ceil(countsM[m]/CHUNK)
        __shared__ int nch[MM];
        for (int m = threadIdx.x; m < MM; m += 256)
            nch[m] = (g_countsM[m] + CHUNK - 1) / CHUNK;
        __syncthreads();
        block_scan_excl<17>(nch, g_chunkStart, MM, &g_workCount);
        if (threadIdx.x == 0) g_chunkStart[MM] = g_workCount;
    }
}

// scatter nodes by cluster + build work list (deterministic, no atomics)
__global__ void scatterM_kernel() {
    int i = blockIdx.x * blockDim.x + threadIdx.x;
    if (i < NTOT) {
        int c = g_cluster[i];
        int pos = g_startsM[c] + atomicAdd(&g_offsM[c], 1);
        g_cmembers[pos] = i;
    }
    if (i < MM) {
        int base = g_chunkStart[i];
        int nch = g_chunkStart[i + 1] - base;
        for (int k = 0; k < nch; k++)
            g_work[base + k] = ((unsigned)i << 12) | (unsigned)k;
    }
}

// balanced pool: one block per <=64-member chunk; partial sums, no atomics
__global__ void pool_kernel(const float* __restrict__ x, const float* __restrict__ xy) {
    int b = blockIdx.x;
    if (b >= g_workCount) return;
    unsigned w = g_work[b];
    int m = (int)(w >> 12);
    int k = (int)(w & 4095u);
    int startC = g_startsM[m];
    int cnt = g_countsM[m];
    int s0 = startC + k * CHUNK;
    int len = min(CHUNK, cnt - k * CHUNK);
    __shared__ int mem[CHUNK];
    int t = threadIdx.x;
    if (t < len) mem[t] = g_cmembers[s0 + t];
    __syncthreads();
    float acc = 0.f;
    int kk = 0;
    for (; kk + 4 <= len; kk += 4) {
        int n0 = mem[kk], n1 = mem[kk + 1], n2 = mem[kk + 2], n3 = mem[kk + 3];
        float a0 = x[(size_t)n0 * CC + t];
        float a1 = x[(size_t)n1 * CC + t];
        float a2 = x[(size_t)n2 * CC + t];
        float a3 = x[(size_t)n3 * CC + t];
        acc += a0 + a1 + a2 + a3;
    }
    for (; kk < len; kk++) acc += x[(size_t)mem[kk] * CC + t];
    g_partial[(size_t)b * CC + t] = acc;
    if (t < 32) {
        float ax = 0.f, ay = 0.f;
        for (int q = t; q < len; q += 32) {
            int node = mem[q];
            ax += xy[(size_t)node * 2];
            ay += xy[(size_t)node * 2 + 1];
        }
        for (int off = 16; off; off >>= 1) {
            ax += __shfl_xor_sync(0xffffffffu, ax, off);
            ay += __shfl_xor_sync(0xffffffffu, ay, off);
        }
        if (t == 0) { g_pxy[b * 2] = ax; g_pxy[b * 2 + 1] = ay; }
    }
}

__global__ void edge_kernel(const int* __restrict__ ei, float* __restrict__ out) {
    for (int e = blockIdx.x * blockDim.x + threadIdx.x; e < EE; e += gridDim.x * blockDim.x) {
        int r = g_cluster[ei[e]];
        int c = g_cluster[ei[EE + e]];
        atomicAdd(&out[OFF_A + (size_t)r * MM + c], 1.0f);
    }
}

// combine partials, divide; emit scalar outputs; diagonal self-loops
__global__ void tail_kernel(float* __restrict__ out) {
    const int TOTXP = MM * CC;
    for (int i = blockIdx.x * blockDim.x + threadIdx.x; i < TOTXP; i += gridDim.x * blockDim.x) {
        int m = i >> 9;
        int c = i & 511;
        int s = g_chunkStart[m], e = g_chunkStart[m + 1];
        float acc = 0.f;
        for (int j = s; j < e; j++) acc += g_partial[(size_t)j * CC + c];
        int cnt = g_countsM[m];
        out[OFF_XPOOL + i] = acc / (float)(cnt > 0 ? cnt : 1);
        if (i < MM * 2) {
            int m2 = i >> 1, coord = i & 1;
            int s2 = g_chunkStart[m2], e2 = g_chunkStart[m2 + 1];
            float a2 = 0.f;
            for (int j = s2; j < e2; j++) a2 += g_pxy[j * 2 + coord];
            int c2 = g_countsM[m2];
            out[OFF_NEWXY + i] = a2 / (float)(c2 > 0 ? c2 : 1);
        }
        if (i < NTOT) {
            out[OFF_CLUST + i] = (float)g_cluster[i];
            float fit;
            if (i == 0) fit = 0.f;
            else if (i <= NN1) fit = g_f1[i - 1];
            else fit = g_f2[i - 1 - NN1];
            out[OFF_FIT + i] = fit;
        }
        if (i < MM) {
            out[OFF_BATCH + i] = 0.f;
            out[OFF_NNT + i] = (i == 0) ? 0.f : ((i <= KK1) ? 1.f : 2.f);
            out[OFF_NTREE + i] = (i == 0) ? -1.f : ((i <= KK1) ? 0.f : (float)((i - 1 - KK1) / 4 + 1));
            atomicAdd(&out[OFF_A + (size_t)i * MM + i], (float)g_countsM[i]);
        }
    }
}

// ---------------- launch ----------------
extern "C" void kernel_launch(void* const* d_in, const int* in_sizes, int n_in,
                              void* d_out, int out_size) {
    const float* x    = (const float*)d_in[0];
    const int*   ei   = (const int*)d_in[1];
    const int*   tree = (const int*)d_in[3];
    const float* xy   = (const float*)d_in[4];
    const float* w1   = (const float*)d_in[5];
    const float* w2   = (const float*)d_in[6];
    float* out = (float*)d_out;

    cudaMemsetAsync(out + OFF_A, 0, (size_t)(MM * (size_t)MM) * sizeof(float), 0);
    setup_kernel<<<32, 256>>>(w1, w2);
    f_kernel<<<((NN1 + NN2) * 32 + 255) / 256, 256>>>(x, w1, w2, tree);
    rank_kernel<<<256, 256>>>(xy);
    cluster1_kernel<<<NN1 / 8, 256>>>(xy);
    parents_kernel<<<NN2 / 256, 256>>>(tree);
    scatter1_kernel<<<NN2 / 256, 256>>>();
    top4_kernel<<<(KK1 * 32 + 255) / 256, 256>>>(xy);
    cluster2_kernel<<<NN2 / 256, 256>>>(xy);
    scatterM_kernel<<<(NTOT + 255) / 256, 256>>>();
    pool_kernel<<<6400, 512>>>(x, xy);
    edge_kernel<<<2048, 256>>>(ei, out);
    tail_kernel<<<2048, 256>>>(out);
}

// round 5
// speedup vs baseline: 1.0558x; 1.0558x over previous
#include <cuda_runtime.h>
#include <math.h>
#include <stdint.h>

#define CC   512
#define NN1  8192
#define NN2  131072
#define NTOT 139265
#define EE   1000000
#define KK1  820
#define KK2  3280
#define MM   4101

// output layout (float32, tuple concatenated)
#define OFF_XPOOL 0ULL
#define OFF_A     2099712ULL
#define OFF_BATCH 18917913ULL
#define OFF_CLUST 18922014ULL
#define OFF_NNT   19061279ULL
#define OFF_NTREE 19065380ULL
#define OFF_FIT   19069481ULL
#define OFF_NEWXY 19208746ULL

// ---------------- device scratch ----------------
__device__ float g_f1[NN1];
__device__ float g_f2[NN2];
__device__ int   g_rank[NN1];
__device__ float g_thr[KK1 * 3];
__device__ int   g_cluster1[NN1];
__device__ int   g_parents[NN2];
__device__ int   g_counts1[KK1];
__device__ int   g_starts1[KK1];
__device__ int   g_gmembers[NN2];
__device__ int   g_cand_idx[KK1 * 4];
__device__ float g_cand_xyf[KK1 * 4 * 3];
__device__ int   g_cluster[NTOT];
__device__ int   g_countsM[MM];
__device__ int   g_startsM[MM];
__device__ int   g_cmembers[NTOT];
__device__ int   g_minTree = 0x7fffffff;   // persistent: atomicMin idempotent across replays
__device__ unsigned g_ctr_rank = 0, g_ctr_par = 0, g_ctr_c2 = 0;  // persistent modulo counters

__device__ __forceinline__ unsigned int f2ord(float f) {
    unsigned int u = __float_as_uint(f);
    return (u & 0x80000000u) ? ~u : (u | 0x80000000u);
}

// exclusive scan of n<=256*PER ints by one 256-thread block
template <int PER>
__device__ void block_scan_excl(const int* __restrict__ in, int* __restrict__ out, int n) {
    __shared__ int sh[256];
    int t = threadIdx.x;
    int base = t * PER;
    int loc[PER];
    int s = 0;
#pragma unroll
    for (int i = 0; i < PER; i++) {
        int v = (base + i < n) ? in[base + i] : 0;
        loc[i] = s; s += v;
    }
    sh[t] = s;
    __syncthreads();
    for (int off = 1; off < 256; off <<= 1) {
        int a = (t >= off) ? sh[t - off] : 0;
        __syncthreads();
        sh[t] += a;
        __syncthreads();
    }
    int prev = (t > 0) ? sh[t - 1] : 0;
#pragma unroll
    for (int i = 0; i < PER; i++)
        if (base + i < n) out[base + i] = prev + loc[i];
}

// one warp per row: f = tanh(dot(x_row, w)/||w||), norm computed in-warp.
// blocks 0..63 also do tree-min (persistent atomicMin); first 8192 threads zero counters.
__global__ void f_kernel(const float* __restrict__ x,
                         const float* __restrict__ w1,
                         const float* __restrict__ w2,
                         const int* __restrict__ tree) {
    int gid = blockIdx.x * blockDim.x + threadIdx.x;
    if (gid < NN1) g_rank[gid] = 0;
    if (gid < KK1) g_counts1[gid] = 0;
    if (gid < MM)  g_countsM[gid] = (gid == 0) ? 1 : 0;
    if (gid == 0)  g_cluster[0] = 0;
    if (blockIdx.x < 64) {
        __shared__ int smin[256];
        int v = 0x7fffffff;
        for (int i = blockIdx.x * 256 + threadIdx.x; i < NN2; i += 64 * 256)
            v = min(v, tree[1 + NN1 + i]);
        smin[threadIdx.x] = v;
        __syncthreads();
        for (int off = 128; off; off >>= 1) {
            if (threadIdx.x < off) smin[threadIdx.x] = min(smin[threadIdx.x], smin[threadIdx.x + off]);
            __syncthreads();
        }
        if (threadIdx.x == 0) atomicMin(&g_minTree, smin[0]);
        __syncthreads();
    }
    int gw = gid >> 5;
    int lane = threadIdx.x & 31;
    if (gw >= NN1 + NN2) return;
    const float4* xr = (const float4*)(x + (size_t)(1 + gw) * CC);
    const float4* wr = (const float4*)((gw < NN1) ? w1 : w2);
    float s = 0.f, wsum = 0.f;
#pragma unroll
    for (int k = 0; k < 4; k++) {
        float4 a = xr[lane + 32 * k];
        float4 b = wr[lane + 32 * k];
        s += a.x * b.x; s += a.y * b.y; s += a.z * b.z; s += a.w * b.w;
        wsum += b.x * b.x + b.y * b.y + b.z * b.z + b.w * b.w;
    }
    for (int off = 16; off; off >>= 1) {
        s    += __shfl_xor_sync(0xffffffffu, s, off);
        wsum += __shfl_xor_sync(0xffffffffu, wsum, off);
    }
    if (lane == 0) {
        float f = tanhf(s / sqrtf(wsum));
        if (gw < NN1) g_f1[gw] = f; else g_f2[gw - NN1] = f;
    }
}

// brute-force stable rank of f1; last block writes thresholds
__global__ void rank_kernel(const float* __restrict__ xy) {
    __shared__ unsigned long long sk[1024];
    int jbase = (blockIdx.x & 7) * 1024;
    int i = (blockIdx.x >> 3) * 256 + threadIdx.x;
    for (int k = threadIdx.x; k < 1024; k += 256) {
        int j = jbase + k;
        sk[k] = ((unsigned long long)f2ord(g_f1[j]) << 32) | (unsigned)j;
    }
    __syncthreads();
    unsigned long long ki = ((unsigned long long)f2ord(g_f1[i]) << 32) | (unsigned)i;
    int c = 0;
#pragma unroll 8
    for (int k = 0; k < 1024; k++) c += (sk[k] < ki) ? 1 : 0;
    atomicAdd(&g_rank[i], c);
    __shared__ bool isLast;
    __threadfence();
    if (threadIdx.x == 0)
        isLast = (atomicAdd(&g_ctr_rank, 1u) % gridDim.x == gridDim.x - 1);
    __syncthreads();
    if (isLast) {
        for (int ii = threadIdx.x; ii < NN1; ii += 256) {
            int r = g_rank[ii];
            if (r % 10 == 0) {
                int s = r / 10;
                g_thr[s * 3 + 0] = xy[(size_t)(1 + ii) * 2];
                g_thr[s * 3 + 1] = xy[(size_t)(1 + ii) * 2 + 1];
                g_thr[s * 3 + 2] = g_f1[ii];
            }
        }
    }
}

// cluster_1: warp per node, lexicographic (d, t) first-min; fused countsM
__global__ void cluster1_kernel(const float* __restrict__ xy) {
    __shared__ float sx[KK1], sy[KK1], sf[KK1];
    for (int k = threadIdx.x; k < KK1; k += blockDim.x) {
        sx[k] = g_thr[k * 3 + 0];
        sy[k] = g_thr[k * 3 + 1];
        sf[k] = g_thr[k * 3 + 2];
    }
    __syncthreads();
    int node = blockIdx.x * 8 + (threadIdx.x >> 5);
    int lane = threadIdx.x & 31;
    if (node >= NN1) return;
    float xj = xy[(size_t)(1 + node) * 2];
    float yj = xy[(size_t)(1 + node) * 2 + 1];
    float fj = g_f1[node];
    float best = INFINITY;
    int bt = KK1;
    for (int t = lane; t < KK1; t += 32) {
        float dx = sx[t] - xj, dy = sy[t] - yj;
        float d = sqrtf(dx * dx + dy * dy) + fabsf(sf[t] - fj);
        if (d < best) { best = d; bt = t; }
    }
    for (int off = 16; off; off >>= 1) {
        float ob = __shfl_xor_sync(0xffffffffu, best, off);
        int   ot = __shfl_xor_sync(0xffffffffu, bt, off);
        if (ob < best || (ob == best && ot < bt)) { best = ob; bt = ot; }
    }
    if (lane == 0) {
        g_cluster1[node] = bt;
        g_cluster[1 + node] = bt + 1;
        atomicAdd(&g_countsM[bt + 1], 1);
    }
}

// parents + group counts; last block does scan0
__global__ void parents_kernel(const int* __restrict__ tree) {
    int i = blockIdx.x * blockDim.x + threadIdx.x;
    int mt = g_minTree;
    if (i < NN2) {
        int p = g_cluster1[tree[1 + NN1 + i] - mt];
        g_parents[i] = p;
        atomicAdd(&g_counts1[p], 1);
    }
    __shared__ bool isLast;
    __threadfence();
    if (threadIdx.x == 0)
        isLast = (atomicAdd(&g_ctr_par, 1u) % gridDim.x == gridDim.x - 1);
    __syncthreads();
    if (isLast) block_scan_excl<4>(g_counts1, g_starts1, KK1);
}

// scatter members: bump starts1 directly (consumers recover start = starts1 - cnt)
__global__ void scatter1_kernel() {
    int i = blockIdx.x * blockDim.x + threadIdx.x;
    if (i >= NN2) return;
    int p = g_parents[i];
    int pos = atomicAdd(&g_starts1[p], 1);
    g_gmembers[pos] = i;
}

// warp-per-group top-4 smallest (comp_key, idx); stable
__global__ void top4_kernel(const float* __restrict__ xy) {
    int g = (blockIdx.x * blockDim.x + threadIdx.x) >> 5;
    int lane = threadIdx.x & 31;
    if (g >= KK1) return;
    int cnt = g_counts1[g];
    int start = g_starts1[g] - cnt;   // starts1 was bumped to end by scatter1
    const unsigned long long SENT = 0xFFFFFFFFFFFFFFFFull;
    unsigned long long best[4] = {SENT, SENT, SENT, SENT};
    float p4 = 4.0f * (float)g;
    for (int k = lane; k < cnt; k += 32) {
        int i = g_gmembers[start + k];
        float key = p4 + g_f2[i];
        unsigned long long v = ((unsigned long long)f2ord(key) << 32) | (unsigned)i;
        if (v < best[3]) {
            if (v < best[0]) { best[3]=best[2]; best[2]=best[1]; best[1]=best[0]; best[0]=v; }
            else if (v < best[1]) { best[3]=best[2]; best[2]=best[1]; best[1]=v; }
            else if (v < best[2]) { best[3]=best[2]; best[2]=v; }
            else best[3]=v;
        }
    }
    int ptr = 0;
    for (int r = 0; r < 4; r++) {
        unsigned long long v = (ptr < 4) ? best[ptr] : SENT;
        unsigned long long m = v;
        for (int off = 16; off; off >>= 1) {
            unsigned long long o = __shfl_xor_sync(0xffffffffu, m, off);
            if (o < m) m = o;
        }
        unsigned ball = __ballot_sync(0xffffffffu, (ptr < 4) && (v == m));
        if (ball) { int src = __ffs(ball) - 1; if (lane == src) ptr++; }
        if (lane == 0) {
            bool valid = (m != SENT);
            int idx = valid ? (int)(unsigned)(m & 0xffffffffULL) : -1;
            g_cand_idx[g * 4 + r] = idx;
            if (valid) {
                g_cand_xyf[(g * 4 + r) * 3 + 0] = xy[(size_t)(1 + NN1 + idx) * 2];
                g_cand_xyf[(g * 4 + r) * 3 + 1] = xy[(size_t)(1 + NN1 + idx) * 2 + 1];
                g_cand_xyf[(g * 4 + r) * 3 + 2] = g_f2[idx];
            }
        }
    }
}

// cluster_2 + countsM; last block does scanM
__global__ void cluster2_kernel(const float* __restrict__ xy) {
    int i = blockIdx.x * blockDim.x + threadIdx.x;
    if (i < NN2) {
        int p = g_parents[i];
        float xi = xy[(size_t)(1 + NN1 + i) * 2];
        float yi = xy[(size_t)(1 + NN1 + i) * 2 + 1];
        float fi = g_f2[i];
        float best = INFINITY;
        int loc = 0;
#pragma unroll
        for (int r = 0; r < 4; r++) {
            int ci = g_cand_idx[p * 4 + r];
            if (ci >= 0) {
                float ax = g_cand_xyf[(p * 4 + r) * 3 + 0];
                float ay = g_cand_xyf[(p * 4 + r) * 3 + 1];
                float af = g_cand_xyf[(p * 4 + r) * 3 + 2];
                float dx = ax - xi, dy = ay - yi;
                float d = sqrtf(dx * dx + dy * dy) + fabsf(af - fi);
                if (d < best) { best = d; loc = r; }
            }
        }
        int c = p * 4 + loc + 1 + KK1;
        g_cluster[1 + NN1 + i] = c;
        atomicAdd(&g_countsM[c], 1);
    }
    __shared__ bool isLast;
    __threadfence();
    if (threadIdx.x == 0)
        isLast = (atomicAdd(&g_ctr_c2, 1u) % gridDim.x == gridDim.x - 1);
    __syncthreads();
    if (isLast) block_scan_excl<17>(g_countsM, g_startsM, MM);
}

// scatter nodes by cluster (bump startsM; consumers recover start = startsM - cnt)
__global__ void scatterM_kernel() {
    int i = blockIdx.x * blockDim.x + threadIdx.x;
    if (i >= NTOT) return;
    int c = g_cluster[i];
    int pos = atomicAdd(&g_startsM[c], 1);
    g_cmembers[pos] = i;
}

// one block per output cluster; 512 threads = one per channel; warp 0 also does xy mean
__global__ void pool_kernel(const float* __restrict__ x, const float* __restrict__ xy,
                            float* __restrict__ out) {
    int m = blockIdx.x;
    int t = threadIdx.x;
    int cnt = g_countsM[m];
    int start = g_startsM[m] - cnt;   // startsM was bumped to end by scatterM
    float acc = 0.f;
    int k = 0;
    for (; k + 4 <= cnt; k += 4) {
        int n0 = g_cmembers[start + k];
        int n1 = g_cmembers[start + k + 1];
        int n2 = g_cmembers[start + k + 2];
        int n3 = g_cmembers[start + k + 3];
        float a0 = x[(size_t)n0 * CC + t];
        float a1 = x[(size_t)n1 * CC + t];
        float a2 = x[(size_t)n2 * CC + t];
        float a3 = x[(size_t)n3 * CC + t];
        acc += a0 + a1 + a2 + a3;
    }
    for (; k < cnt; k++) {
        int n0 = g_cmembers[start + k];
        acc += x[(size_t)n0 * CC + t];
    }
    float inv = 1.0f / (float)(cnt > 0 ? cnt : 1);
    out[OFF_XPOOL + (size_t)m * CC + t] = acc * inv;
    if (t < 32) {
        float ax = 0.f, ay = 0.f;
        for (int kk = t; kk < cnt; kk += 32) {
            int node = g_cmembers[start + kk];
            ax += xy[(size_t)node * 2];
            ay += xy[(size_t)node * 2 + 1];
        }
        for (int off = 16; off; off >>= 1) {
            ax += __shfl_xor_sync(0xffffffffu, ax, off);
            ay += __shfl_xor_sync(0xffffffffu, ay, off);
        }
        if (t == 0) {
            out[OFF_NEWXY + (size_t)m * 2]     = ax * inv;
            out[OFF_NEWXY + (size_t)m * 2 + 1] = ay * inv;
        }
    }
}

__global__ void edge_kernel(const int* __restrict__ ei, float* __restrict__ out) {
    for (int e = blockIdx.x * blockDim.x + threadIdx.x; e < EE; e += gridDim.x * blockDim.x) {
        int r = g_cluster[ei[e]];
        int c = g_cluster[ei[EE + e]];
        atomicAdd(&out[OFF_A + (size_t)r * MM + c], 1.0f);
    }
}

__global__ void tail_kernel(float* __restrict__ out) {
    for (int i = blockIdx.x * blockDim.x + threadIdx.x; i < NTOT; i += gridDim.x * blockDim.x) {
        out[OFF_CLUST + i] = (float)g_cluster[i];
        float fit;
        if (i == 0) fit = 0.f;
        else if (i <= NN1) fit = g_f1[i - 1];
        else fit = g_f2[i - 1 - NN1];
        out[OFF_FIT + i] = fit;
        if (i < MM) {
            out[OFF_BATCH + i] = 0.f;
            out[OFF_NNT + i] = (i == 0) ? 0.f : ((i <= KK1) ? 1.f : 2.f);
            out[OFF_NTREE + i] = (i == 0) ? -1.f : ((i <= KK1) ? 0.f : (float)((i - 1 - KK1) / 4 + 1));
            atomicAdd(&out[OFF_A + (size_t)i * MM + i], (float)g_countsM[i]);
        }
    }
}

// ---------------- launch ----------------
extern "C" void kernel_launch(void* const* d_in, const int* in_sizes, int n_in,
                              void* d_out, int out_size) {
    const float* x    = (const float*)d_in[0];
    const int*   ei   = (const int*)d_in[1];
    const int*   tree = (const int*)d_in[3];
    const float* xy   = (const float*)d_in[4];
    const float* w1   = (const float*)d_in[5];
    const float* w2   = (const float*)d_in[6];
    float* out = (float*)d_out;

    cudaMemsetAsync(out + OFF_A, 0, (size_t)MM * MM * sizeof(float), 0);
    f_kernel<<<((NN1 + NN2) * 32 + 255) / 256, 256>>>(x, w1, w2, tree);
    rank_kernel<<<256, 256>>>(xy);
    cluster1_kernel<<<NN1 / 8, 256>>>(xy);
    parents_kernel<<<NN2 / 256, 256>>>(tree);
    scatter1_kernel<<<NN2 / 256, 256>>>();
    top4_kernel<<<(KK1 * 32 + 255) / 256, 256>>>(xy);
    cluster2_kernel<<<NN2 / 256, 256>>>(xy);
    scatterM_kernel<<<(NTOT + 255) / 256, 256>>>();
    pool_kernel<<<MM, 512>>>(x, xy, out);
    edge_kernel<<<2048, 256>>>(ei, out);
    tail_kernel<<<(NTOT + 255) / 256, 256>>>(out);
}

// round 7
// speedup vs baseline: 1.1522x; 1.0913x over previous
#include <cuda_runtime.h>
#include <math.h>
#include <stdint.h>

#define CC   512
#define NN1  8192
#define NN2  131072
#define NTOT 139265
#define EE   1000000
#define KK1  820
#define KK2  3280
#define MM   4101

// output layout (float32, tuple concatenated)
#define OFF_XPOOL 0ULL
#define OFF_A     2099712ULL
#define OFF_BATCH 18917913ULL
#define OFF_CLUST 18922014ULL
#define OFF_NNT   19061279ULL
#define OFF_NTREE 19065380ULL
#define OFF_FIT   19069481ULL
#define OFF_NEWXY 19208746ULL

// ---------------- device scratch ----------------
__device__ float g_f1[NN1];
__device__ float g_f2[NN2];
__device__ int   g_rank[NN1];
__device__ float g_thr[KK1 * 3];
__device__ int   g_cluster1[NN1];
__device__ int   g_parents[NN2];
__device__ int   g_counts1[KK1];
__device__ int   g_starts1[KK1];
__device__ int   g_gmembers[NN2];
__device__ int   g_cand_idx[KK1 * 4];
__device__ float g_cand_xyf[KK1 * 4 * 3];
__device__ int   g_cluster[NTOT];
__device__ int   g_countsM[MM];
__device__ int   g_startsM[MM];
__device__ int   g_cmembers[NTOT];
__device__ int   g_minTree = 0x7fffffff;   // persistent: atomicMin idempotent across replays

__device__ __forceinline__ unsigned int f2ord(float f) {
    unsigned int u = __float_as_uint(f);
    return (u & 0x80000000u) ? ~u : (u | 0x80000000u);
}

// ---------------- f: fitness + zero counters + tree-min + in-warp weight norm
__global__ void f_kernel(const float* __restrict__ x,
                         const float* __restrict__ w1,
                         const float* __restrict__ w2,
                         const int* __restrict__ tree) {
    int gid = blockIdx.x * blockDim.x + threadIdx.x;
    if (gid < NN1) g_rank[gid] = 0;
    if (gid < KK1) g_counts1[gid] = 0;
    if (gid < MM)  g_countsM[gid] = (gid == 0) ? 1 : 0;
    if (gid == 0)  g_cluster[0] = 0;
    if (blockIdx.x < 64) {
        __shared__ int smin[256];
        int v = 0x7fffffff;
        for (int i = blockIdx.x * 256 + threadIdx.x; i < NN2; i += 64 * 256)
            v = min(v, tree[1 + NN1 + i]);
        smin[threadIdx.x] = v;
        __syncthreads();
        for (int off = 128; off; off >>= 1) {
            if (threadIdx.x < off) smin[threadIdx.x] = min(smin[threadIdx.x], smin[threadIdx.x + off]);
            __syncthreads();
        }
        if (threadIdx.x == 0) atomicMin(&g_minTree, smin[0]);
        __syncthreads();
    }
    int gw = gid >> 5;
    int lane = threadIdx.x & 31;
    if (gw >= NN1 + NN2) return;
    const float4* xr = (const float4*)(x + (size_t)(1 + gw) * CC);
    const float4* wr = (const float4*)((gw < NN1) ? w1 : w2);
    float s = 0.f, wsum = 0.f;
#pragma unroll
    for (int k = 0; k < 4; k++) {
        float4 a = xr[lane + 32 * k];
        float4 b = wr[lane + 32 * k];
        s += a.x * b.x; s += a.y * b.y; s += a.z * b.z; s += a.w * b.w;
        wsum += b.x * b.x + b.y * b.y + b.z * b.z + b.w * b.w;
    }
    for (int off = 16; off; off >>= 1) {
        s    += __shfl_xor_sync(0xffffffffu, s, off);
        wsum += __shfl_xor_sync(0xffffffffu, wsum, off);
    }
    if (lane == 0) {
        float f = tanhf(s / sqrtf(wsum));
        if (gw < NN1) g_f1[gw] = f; else g_f2[gw - NN1] = f;
    }
}

// brute-force stable rank of f1 (composite u64 keys)
__global__ void rank_kernel() {
    __shared__ unsigned long long sk[1024];
    int jbase = (blockIdx.x & 7) * 1024;
    int i = (blockIdx.x >> 3) * 256 + threadIdx.x;
    for (int k = threadIdx.x; k < 1024; k += 256) {
        int j = jbase + k;
        sk[k] = ((unsigned long long)f2ord(g_f1[j]) << 32) | (unsigned)j;
    }
    __syncthreads();
    unsigned long long ki = ((unsigned long long)f2ord(g_f1[i]) << 32) | (unsigned)i;
    int c = 0;
#pragma unroll 8
    for (int k = 0; k < 1024; k++) c += (sk[k] < ki) ? 1 : 0;
    atomicAdd(&g_rank[i], c);
}

// rank % 10 == 0 -> threshold slot rank/10
__global__ void thr_kernel(const float* __restrict__ xy) {
    int i = blockIdx.x * blockDim.x + threadIdx.x;
    if (i >= NN1) return;
    int r = g_rank[i];
    if (r % 10 == 0) {
        int s = r / 10;
        g_thr[s * 3 + 0] = xy[(size_t)(1 + i) * 2];
        g_thr[s * 3 + 1] = xy[(size_t)(1 + i) * 2 + 1];
        g_thr[s * 3 + 2] = g_f1[i];
    }
}

// cluster_1: warp per node, lexicographic (d, t) first-min; fused countsM
__global__ void cluster1_kernel(const float* __restrict__ xy) {
    __shared__ float sx[KK1], sy[KK1], sf[KK1];
    for (int k = threadIdx.x; k < KK1; k += blockDim.x) {
        sx[k] = g_thr[k * 3 + 0];
        sy[k] = g_thr[k * 3 + 1];
        sf[k] = g_thr[k * 3 + 2];
    }
    __syncthreads();
    int node = blockIdx.x * 8 + (threadIdx.x >> 5);
    int lane = threadIdx.x & 31;
    if (node >= NN1) return;
    float xj = xy[(size_t)(1 + node) * 2];
    float yj = xy[(size_t)(1 + node) * 2 + 1];
    float fj = g_f1[node];
    float best = INFINITY;
    int bt = KK1;
    for (int t = lane; t < KK1; t += 32) {
        float dx = sx[t] - xj, dy = sy[t] - yj;
        float d = sqrtf(dx * dx + dy * dy) + fabsf(sf[t] - fj);
        if (d < best) { best = d; bt = t; }
    }
    for (int off = 16; off; off >>= 1) {
        float ob = __shfl_xor_sync(0xffffffffu, best, off);
        int   ot = __shfl_xor_sync(0xffffffffu, bt, off);
        if (ob < best || (ob == best && ot < bt)) { best = ob; bt = ot; }
    }
    if (lane == 0) {
        g_cluster1[node] = bt;
        g_cluster[1 + node] = bt + 1;
        atomicAdd(&g_countsM[bt + 1], 1);
    }
}

__global__ void parents_kernel(const int* __restrict__ tree) {
    int i = blockIdx.x * blockDim.x + threadIdx.x;
    if (i >= NN2) return;
    int p = g_cluster1[tree[1 + NN1 + i] - g_minTree];
    g_parents[i] = p;
    atomicAdd(&g_counts1[p], 1);
}

// single-block exclusive scan over device symbols (which=0: counts1->starts1; 1: countsM->startsM)
__global__ void scan_kernel(int which) {
    __shared__ int sh[256];
    const int* in = which ? g_countsM : g_counts1;
    int* out = which ? g_startsM : g_starts1;
    int n = which ? MM : KK1;
    const int PER = 17;                      // 256*17 = 4352 >= MM
    int t = threadIdx.x;
    int base = t * PER;
    int loc[PER];
    int s = 0;
#pragma unroll
    for (int i = 0; i < PER; i++) {
        int v = (base + i < n) ? in[base + i] : 0;
        loc[i] = s; s += v;
    }
    sh[t] = s;
    __syncthreads();
    for (int off = 1; off < 256; off <<= 1) {
        int a = (t >= off) ? sh[t - off] : 0;
        __syncthreads();
        sh[t] += a;
        __syncthreads();
    }
    int prev = (t > 0) ? sh[t - 1] : 0;
#pragma unroll
    for (int i = 0; i < PER; i++)
        if (base + i < n) out[base + i] = prev + loc[i];
}

// scatter members: bump starts1 directly (consumers recover start = starts1 - cnt)
__global__ void scatter1_kernel() {
    int i = blockIdx.x * blockDim.x + threadIdx.x;
    if (i >= NN2) return;
    int p = g_parents[i];
    int pos = atomicAdd(&g_starts1[p], 1);
    g_gmembers[pos] = i;
}

// warp-per-group top-4 smallest (comp_key, idx); stable
__global__ void top4_kernel(const float* __restrict__ xy) {
    int g = (blockIdx.x * blockDim.x + threadIdx.x) >> 5;
    int lane = threadIdx.x & 31;
    if (g >= KK1) return;
    int cnt = g_counts1[g];
    int start = g_starts1[g] - cnt;
    const unsigned long long SENT = 0xFFFFFFFFFFFFFFFFull;
    unsigned long long best[4] = {SENT, SENT, SENT, SENT};
    float p4 = 4.0f * (float)g;
    for (int k = lane; k < cnt; k += 32) {
        int i = g_gmembers[start + k];
        float key = p4 + g_f2[i];
        unsigned long long v = ((unsigned long long)f2ord(key) << 32) | (unsigned)i;
        if (v < best[3]) {
            if (v < best[0]) { best[3]=best[2]; best[2]=best[1]; best[1]=best[0]; best[0]=v; }
            else if (v < best[1]) { best[3]=best[2]; best[2]=best[1]; best[1]=v; }
            else if (v < best[2]) { best[3]=best[2]; best[2]=v; }
            else best[3]=v;
        }
    }
    int ptr = 0;
    for (int r = 0; r < 4; r++) {
        unsigned long long v = (ptr < 4) ? best[ptr] : SENT;
        unsigned long long m = v;
        for (int off = 16; off; off >>= 1) {
            unsigned long long o = __shfl_xor_sync(0xffffffffu, m, off);
            if (o < m) m = o;
        }
        unsigned ball = __ballot_sync(0xffffffffu, (ptr < 4) && (v == m));
        if (ball) { int src = __ffs(ball) - 1; if (lane == src) ptr++; }
        if (lane == 0) {
            bool valid = (m != SENT);
            int idx = valid ? (int)(unsigned)(m & 0xffffffffULL) : -1;
            g_cand_idx[g * 4 + r] = idx;
            if (valid) {
                g_cand_xyf[(g * 4 + r) * 3 + 0] = xy[(size_t)(1 + NN1 + idx) * 2];
                g_cand_xyf[(g * 4 + r) * 3 + 1] = xy[(size_t)(1 + NN1 + idx) * 2 + 1];
                g_cand_xyf[(g * 4 + r) * 3 + 2] = g_f2[idx];
            }
        }
    }
}

// cluster_2 + fused countsM
__global__ void cluster2_kernel(const float* __restrict__ xy) {
    int i = blockIdx.x * blockDim.x + threadIdx.x;
    if (i >= NN2) return;
    int p = g_parents[i];
    float xi = xy[(size_t)(1 + NN1 + i) * 2];
    float yi = xy[(size_t)(1 + NN1 + i) * 2 + 1];
    float fi = g_f2[i];
    float best = INFINITY;
    int loc = 0;
#pragma unroll
    for (int r = 0; r < 4; r++) {
        int ci = g_cand_idx[p * 4 + r];
        if (ci >= 0) {
            float ax = g_cand_xyf[(p * 4 + r) * 3 + 0];
            float ay = g_cand_xyf[(p * 4 + r) * 3 + 1];
            float af = g_cand_xyf[(p * 4 + r) * 3 + 2];
            float dx = ax - xi, dy = ay - yi;
            float d = sqrtf(dx * dx + dy * dy) + fabsf(af - fi);
            if (d < best) { best = d; loc = r; }
        }
    }
    int c = p * 4 + loc + 1 + KK1;
    g_cluster[1 + NN1 + i] = c;
    atomicAdd(&g_countsM[c], 1);
}

// scatter nodes by cluster (bump startsM; consumers recover start = startsM - cnt)
__global__ void scatterM_kernel() {
    int i = blockIdx.x * blockDim.x + threadIdx.x;
    if (i >= NTOT) return;
    int c = g_cluster[i];
    int pos = atomicAdd(&g_startsM[c], 1);
    g_cmembers[pos] = i;
}

// one block per output cluster; 512 threads = one per channel; warp 0 also does xy mean
__global__ void pool_kernel(const float* __restrict__ x, const float* __restrict__ xy,
                            float* __restrict__ out) {
    int m = blockIdx.x;
    int t = threadIdx.x;
    int cnt = g_countsM[m];
    int start = g_startsM[m] - cnt;
    float acc = 0.f;
    int k = 0;
    for (; k + 4 <= cnt; k += 4) {
        int n0 = g_cmembers[start + k];
        int n1 = g_cmembers[start + k + 1];
        int n2 = g_cmembers[start + k + 2];
        int n3 = g_cmembers[start + k + 3];
        float a0 = x[(size_t)n0 * CC + t];
        float a1 = x[(size_t)n1 * CC + t];
        float a2 = x[(size_t)n2 * CC + t];
        float a3 = x[(size_t)n3 * CC + t];
        acc += a0 + a1 + a2 + a3;
    }
    for (; k < cnt; k++) {
        int n0 = g_cmembers[start + k];
        acc += x[(size_t)n0 * CC + t];
    }
    float inv = 1.0f / (float)(cnt > 0 ? cnt : 1);
    out[OFF_XPOOL + (size_t)m * CC + t] = acc * inv;
    if (t < 32) {
        float ax = 0.f, ay = 0.f;
        for (int kk = t; kk < cnt; kk += 32) {
            int node = g_cmembers[start + kk];
            ax += xy[(size_t)node * 2];
            ay += xy[(size_t)node * 2 + 1];
        }
        for (int off = 16; off; off >>= 1) {
            ax += __shfl_xor_sync(0xffffffffu, ax, off);
            ay += __shfl_xor_sync(0xffffffffu, ay, off);
        }
        if (t == 0) {
            out[OFF_NEWXY + (size_t)m * 2]     = ax * inv;
            out[OFF_NEWXY + (size_t)m * 2 + 1] = ay * inv;
        }
    }
}

__global__ void edge_kernel(const int* __restrict__ ei, float* __restrict__ out) {
    for (int e = blockIdx.x * blockDim.x + threadIdx.x; e < EE; e += gridDim.x * blockDim.x) {
        int r = g_cluster[ei[e]];
        int c = g_cluster[ei[EE + e]];
        atomicAdd(&out[OFF_A + (size_t)r * MM + c], 1.0f);
    }
}

__global__ void tail_kernel(float* __restrict__ out) {
    for (int i = blockIdx.x * blockDim.x + threadIdx.x; i < NTOT; i += gridDim.x * blockDim.x) {
        out[OFF_CLUST + i] = (float)g_cluster[i];
        float fit;
        if (i == 0) fit = 0.f;
        else if (i <= NN1) fit = g_f1[i - 1];
        else fit = g_f2[i - 1 - NN1];
        out[OFF_FIT + i] = fit;
        if (i < MM) {
            out[OFF_BATCH + i] = 0.f;
            out[OFF_NNT + i] = (i == 0) ? 0.f : ((i <= KK1) ? 1.f : 2.f);
            out[OFF_NTREE + i] = (i == 0) ? -1.f : ((i <= KK1) ? 0.f : (float)((i - 1 - KK1) / 4 + 1));
            atomicAdd(&out[OFF_A + (size_t)i * MM + i], (float)g_countsM[i]);
        }
    }
}

// ---------------- launch ----------------
extern "C" void kernel_launch(void* const* d_in, const int* in_sizes, int n_in,
                              void* d_out, int out_size) {
    const float* x    = (const float*)d_in[0];
    const int*   ei   = (const int*)d_in[1];
    const int*   tree = (const int*)d_in[3];
    const float* xy   = (const float*)d_in[4];
    const float* w1   = (const float*)d_in[5];
    const float* w2   = (const float*)d_in[6];
    float* out = (float*)d_out;

    static cudaStream_t s1 = nullptr;
    static cudaEvent_t eFork = nullptr, eMs = nullptr;
    if (!s1) {
        cudaStreamCreateWithFlags(&s1, cudaStreamNonBlocking);
        cudaEventCreateWithFlags(&eFork, cudaEventDisableTiming);
        cudaEventCreateWithFlags(&eMs, cudaEventDisableTiming);
    }

    // A memset overlaps the whole clustering chain; joined before pool/edge/tail
    cudaEventRecord(eFork, 0);
    cudaStreamWaitEvent(s1, eFork, 0);
    cudaMemsetAsync(out + OFF_A, 0, (size_t)MM * MM * sizeof(float), s1);
    cudaEventRecord(eMs, s1);

    f_kernel<<<((NN1 + NN2) * 32 + 255) / 256, 256>>>(x, w1, w2, tree);
    rank_kernel<<<256, 256>>>();
    thr_kernel<<<32, 256>>>(xy);
    cluster1_kernel<<<NN1 / 8, 256>>>(xy);
    parents_kernel<<<NN2 / 256, 256>>>(tree);
    scan_kernel<<<1, 256>>>(0);
    scatter1_kernel<<<NN2 / 256, 256>>>();
    top4_kernel<<<(KK1 * 32 + 255) / 256, 256>>>(xy);
    cluster2_kernel<<<NN2 / 256, 256>>>(xy);
    scan_kernel<<<1, 256>>>(1);
    scatterM_kernel<<<(NTOT + 255) / 256, 256>>>();
    cudaStreamWaitEvent(0, eMs, 0);
    pool_kernel<<<MM, 512>>>(x, xy, out);
    edge_kernel<<<2048, 256>>>(ei, out);
    tail_kernel<<<(NTOT + 255) / 256, 256>>>(out);
}

// round 8
// speedup vs baseline: 1.2112x; 1.0512x over previous
#include <cuda_runtime.h>
#include <math.h>
#include <stdint.h>

#define CC   512
#define NN1  8192
#define NN2  131072
#define NTOT 139265
#define EE   1000000
#define KK1  820
#define KK2  3280
#define MM   4101

// output layout (float32, tuple concatenated)
#define OFF_XPOOL 0ULL
#define OFF_A     2099712ULL
#define OFF_BATCH 18917913ULL
#define OFF_CLUST 18922014ULL
#define OFF_NNT   19061279ULL
#define OFF_NTREE 19065380ULL
#define OFF_FIT   19069481ULL
#define OFF_NEWXY 19208746ULL

// ---------------- device scratch ----------------
__device__ float g_f1[NN1];
__device__ float g_f2[NN2];
__device__ int   g_rank[NN1];
__device__ float g_thr[KK1 * 3];
__device__ int   g_cluster1[NN1];
__device__ int   g_parents[NN2];
__device__ int   g_counts1[KK1];
__device__ int   g_starts1[KK1];
__device__ int   g_gmembers[NN2];
__device__ int   g_cand_idx[KK1 * 4];
__device__ float g_cand_xyf[KK1 * 4 * 3];
__device__ int   g_cluster[NTOT];
__device__ int   g_countsM[MM];
__device__ int   g_startsM[MM];
__device__ int   g_cmembers[NTOT];
__device__ int   g_minTree = 0x7fffffff;   // persistent: atomicMin idempotent across replays

__device__ __forceinline__ unsigned int f2ord(float f) {
    unsigned int u = __float_as_uint(f);
    return (u & 0x80000000u) ? ~u : (u | 0x80000000u);
}

// ---------------- f1: first 8192 fitness rows + zero counters + tree-min
__global__ void f1_kernel(const float* __restrict__ x,
                          const float* __restrict__ w1,
                          const int* __restrict__ tree) {
    int gid = blockIdx.x * blockDim.x + threadIdx.x;   // 1024 blocks * 256 = 262144
    if (gid < NN1) g_rank[gid] = 0;
    if (gid < KK1) g_counts1[gid] = 0;
    if (gid < MM)  g_countsM[gid] = (gid == 0) ? 1 : 0;
    if (gid == 0)  g_cluster[0] = 0;
    if (blockIdx.x < 64) {
        __shared__ int smin[256];
        int v = 0x7fffffff;
        for (int i = blockIdx.x * 256 + threadIdx.x; i < NN2; i += 64 * 256)
            v = min(v, tree[1 + NN1 + i]);
        smin[threadIdx.x] = v;
        __syncthreads();
        for (int off = 128; off; off >>= 1) {
            if (threadIdx.x < off) smin[threadIdx.x] = min(smin[threadIdx.x], smin[threadIdx.x + off]);
            __syncthreads();
        }
        if (threadIdx.x == 0) atomicMin(&g_minTree, smin[0]);
        __syncthreads();
    }
    int gw = gid >> 5;
    int lane = threadIdx.x & 31;
    if (gw >= NN1) return;
    const float4* xr = (const float4*)(x + (size_t)(1 + gw) * CC);
    const float4* wr = (const float4*)w1;
    float s = 0.f, wsum = 0.f;
#pragma unroll
    for (int k = 0; k < 4; k++) {
        float4 a = xr[lane + 32 * k];
        float4 b = wr[lane + 32 * k];
        s += a.x * b.x; s += a.y * b.y; s += a.z * b.z; s += a.w * b.w;
        wsum += b.x * b.x + b.y * b.y + b.z * b.z + b.w * b.w;
    }
    for (int off = 16; off; off >>= 1) {
        s    += __shfl_xor_sync(0xffffffffu, s, off);
        wsum += __shfl_xor_sync(0xffffffffu, wsum, off);
    }
    if (lane == 0) g_f1[gw] = tanhf(s / sqrtf(wsum));
}

// ---------------- f2: remaining 131072 fitness rows
__global__ void f2_kernel(const float* __restrict__ x, const float* __restrict__ w2) {
    int gw = (blockIdx.x * blockDim.x + threadIdx.x) >> 5;
    int lane = threadIdx.x & 31;
    if (gw >= NN2) return;
    const float4* xr = (const float4*)(x + (size_t)(1 + NN1 + gw) * CC);
    const float4* wr = (const float4*)w2;
    float s = 0.f, wsum = 0.f;
#pragma unroll
    for (int k = 0; k < 4; k++) {
        float4 a = xr[lane + 32 * k];
        float4 b = wr[lane + 32 * k];
        s += a.x * b.x; s += a.y * b.y; s += a.z * b.z; s += a.w * b.w;
        wsum += b.x * b.x + b.y * b.y + b.z * b.z + b.w * b.w;
    }
    for (int off = 16; off; off >>= 1) {
        s    += __shfl_xor_sync(0xffffffffu, s, off);
        wsum += __shfl_xor_sync(0xffffffffu, wsum, off);
    }
    if (lane == 0) g_f2[gw] = tanhf(s / sqrtf(wsum));
}

// brute-force stable rank of f1 (composite u64 keys)
__global__ void rank_kernel() {
    __shared__ unsigned long long sk[1024];
    int jbase = (blockIdx.x & 7) * 1024;
    int i = (blockIdx.x >> 3) * 256 + threadIdx.x;
    for (int k = threadIdx.x; k < 1024; k += 256) {
        int j = jbase + k;
        sk[k] = ((unsigned long long)f2ord(g_f1[j]) << 32) | (unsigned)j;
    }
    __syncthreads();
    unsigned long long ki = ((unsigned long long)f2ord(g_f1[i]) << 32) | (unsigned)i;
    int c = 0;
#pragma unroll 8
    for (int k = 0; k < 1024; k++) c += (sk[k] < ki) ? 1 : 0;
    atomicAdd(&g_rank[i], c);
}

// rank % 10 == 0 -> threshold slot rank/10
__global__ void thr_kernel(const float* __restrict__ xy) {
    int i = blockIdx.x * blockDim.x + threadIdx.x;
    if (i >= NN1) return;
    int r = g_rank[i];
    if (r % 10 == 0) {
        int s = r / 10;
        g_thr[s * 3 + 0] = xy[(size_t)(1 + i) * 2];
        g_thr[s * 3 + 1] = xy[(size_t)(1 + i) * 2 + 1];
        g_thr[s * 3 + 2] = g_f1[i];
    }
}

// cluster_1: warp per node, lexicographic (d, t) first-min; fused countsM
__global__ void cluster1_kernel(const float* __restrict__ xy) {
    __shared__ float sx[KK1], sy[KK1], sf[KK1];
    for (int k = threadIdx.x; k < KK1; k += blockDim.x) {
        sx[k] = g_thr[k * 3 + 0];
        sy[k] = g_thr[k * 3 + 1];
        sf[k] = g_thr[k * 3 + 2];
    }
    __syncthreads();
    int node = blockIdx.x * 8 + (threadIdx.x >> 5);
    int lane = threadIdx.x & 31;
    if (node >= NN1) return;
    float xj = xy[(size_t)(1 + node) * 2];
    float yj = xy[(size_t)(1 + node) * 2 + 1];
    float fj = g_f1[node];
    float best = INFINITY;
    int bt = KK1;
    for (int t = lane; t < KK1; t += 32) {
        float dx = sx[t] - xj, dy = sy[t] - yj;
        float d = sqrtf(dx * dx + dy * dy) + fabsf(sf[t] - fj);
        if (d < best) { best = d; bt = t; }
    }
    for (int off = 16; off; off >>= 1) {
        float ob = __shfl_xor_sync(0xffffffffu, best, off);
        int   ot = __shfl_xor_sync(0xffffffffu, bt, off);
        if (ob < best || (ob == best && ot < bt)) { best = ob; bt = ot; }
    }
    if (lane == 0) {
        g_cluster1[node] = bt;
        g_cluster[1 + node] = bt + 1;
        atomicAdd(&g_countsM[bt + 1], 1);
    }
}

__global__ void parents_kernel(const int* __restrict__ tree) {
    int i = blockIdx.x * blockDim.x + threadIdx.x;
    if (i >= NN2) return;
    int p = g_cluster1[tree[1 + NN1 + i] - g_minTree];
    g_parents[i] = p;
    atomicAdd(&g_counts1[p], 1);
}

// single-block exclusive scan over device symbols (which=0: counts1->starts1; 1: countsM->startsM)
__global__ void scan_kernel(int which) {
    __shared__ int sh[256];
    const int* in = which ? g_countsM : g_counts1;
    int* out = which ? g_startsM : g_starts1;
    int n = which ? MM : KK1;
    const int PER = 17;
    int t = threadIdx.x;
    int base = t * PER;
    int loc[PER];
    int s = 0;
#pragma unroll
    for (int i = 0; i < PER; i++) {
        int v = (base + i < n) ? in[base + i] : 0;
        loc[i] = s; s += v;
    }
    sh[t] = s;
    __syncthreads();
    for (int off = 1; off < 256; off <<= 1) {
        int a = (t >= off) ? sh[t - off] : 0;
        __syncthreads();
        sh[t] += a;
        __syncthreads();
    }
    int prev = (t > 0) ? sh[t - 1] : 0;
#pragma unroll
    for (int i = 0; i < PER; i++)
        if (base + i < n) out[base + i] = prev + loc[i];
}

// scatter members: bump starts1 directly (consumers recover start = starts1 - cnt)
__global__ void scatter1_kernel() {
    int i = blockIdx.x * blockDim.x + threadIdx.x;
    if (i >= NN2) return;
    int p = g_parents[i];
    int pos = atomicAdd(&g_starts1[p], 1);
    g_gmembers[pos] = i;
}

// warp-per-group top-4 smallest (comp_key, idx); stable
__global__ void top4_kernel(const float* __restrict__ xy) {
    int g = (blockIdx.x * blockDim.x + threadIdx.x) >> 5;
    int lane = threadIdx.x & 31;
    if (g >= KK1) return;
    int cnt = g_counts1[g];
    int start = g_starts1[g] - cnt;
    const unsigned long long SENT = 0xFFFFFFFFFFFFFFFFull;
    unsigned long long best[4] = {SENT, SENT, SENT, SENT};
    float p4 = 4.0f * (float)g;
    for (int k = lane; k < cnt; k += 32) {
        int i = g_gmembers[start + k];
        float key = p4 + g_f2[i];
        unsigned long long v = ((unsigned long long)f2ord(key) << 32) | (unsigned)i;
        if (v < best[3]) {
            if (v < best[0]) { best[3]=best[2]; best[2]=best[1]; best[1]=best[0]; best[0]=v; }
            else if (v < best[1]) { best[3]=best[2]; best[2]=best[1]; best[1]=v; }
            else if (v < best[2]) { best[3]=best[2]; best[2]=v; }
            else best[3]=v;
        }
    }
    int ptr = 0;
    for (int r = 0; r < 4; r++) {
        unsigned long long v = (ptr < 4) ? best[ptr] : SENT;
        unsigned long long m = v;
        for (int off = 16; off; off >>= 1) {
            unsigned long long o = __shfl_xor_sync(0xffffffffu, m, off);
            if (o < m) m = o;
        }
        unsigned ball = __ballot_sync(0xffffffffu, (ptr < 4) && (v == m));
        if (ball) { int src = __ffs(ball) - 1; if (lane == src) ptr++; }
        if (lane == 0) {
            bool valid = (m != SENT);
            int idx = valid ? (int)(unsigned)(m & 0xffffffffULL) : -1;
            g_cand_idx[g * 4 + r] = idx;
            if (valid) {
                g_cand_xyf[(g * 4 + r) * 3 + 0] = xy[(size_t)(1 + NN1 + idx) * 2];
                g_cand_xyf[(g * 4 + r) * 3 + 1] = xy[(size_t)(1 + NN1 + idx) * 2 + 1];
                g_cand_xyf[(g * 4 + r) * 3 + 2] = g_f2[idx];
            }
        }
    }
}

// cluster_2 + fused countsM
__global__ void cluster2_kernel(const float* __restrict__ xy) {
    int i = blockIdx.x * blockDim.x + threadIdx.x;
    if (i >= NN2) return;
    int p = g_parents[i];
    float xi = xy[(size_t)(1 + NN1 + i) * 2];
    float yi = xy[(size_t)(1 + NN1 + i) * 2 + 1];
    float fi = g_f2[i];
    float best = INFINITY;
    int loc = 0;
#pragma unroll
    for (int r = 0; r < 4; r++) {
        int ci = g_cand_idx[p * 4 + r];
        if (ci >= 0) {
            float ax = g_cand_xyf[(p * 4 + r) * 3 + 0];
            float ay = g_cand_xyf[(p * 4 + r) * 3 + 1];
            float af = g_cand_xyf[(p * 4 + r) * 3 + 2];
            float dx = ax - xi, dy = ay - yi;
            float d = sqrtf(dx * dx + dy * dy) + fabsf(af - fi);
            if (d < best) { best = d; loc = r; }
        }
    }
    int c = p * 4 + loc + 1 + KK1;
    g_cluster[1 + NN1 + i] = c;
    atomicAdd(&g_countsM[c], 1);
}

// scatter nodes by cluster (bump startsM; consumers recover start = startsM - cnt)
__global__ void scatterM_kernel() {
    int i = blockIdx.x * blockDim.x + threadIdx.x;
    if (i >= NTOT) return;
    int c = g_cluster[i];
    int pos = atomicAdd(&g_startsM[c], 1);
    g_cmembers[pos] = i;
}

// one block per cluster; 128 threads, float4 per thread (512 channels); warp 0 does xy mean
__global__ void pool_kernel(const float* __restrict__ x, const float* __restrict__ xy,
                            float* __restrict__ out) {
    int m = blockIdx.x;
    int t = threadIdx.x;
    int cnt = g_countsM[m];
    int start = g_startsM[m] - cnt;
    float4 acc = make_float4(0.f, 0.f, 0.f, 0.f);
    int k = 0;
    for (; k + 4 <= cnt; k += 4) {
        int n0 = g_cmembers[start + k];
        int n1 = g_cmembers[start + k + 1];
        int n2 = g_cmembers[start + k + 2];
        int n3 = g_cmembers[start + k + 3];
        float4 a0 = ((const float4*)(x + (size_t)n0 * CC))[t];
        float4 a1 = ((const float4*)(x + (size_t)n1 * CC))[t];
        float4 a2 = ((const float4*)(x + (size_t)n2 * CC))[t];
        float4 a3 = ((const float4*)(x + (size_t)n3 * CC))[t];
        acc.x += a0.x + a1.x + a2.x + a3.x;
        acc.y += a0.y + a1.y + a2.y + a3.y;
        acc.z += a0.z + a1.z + a2.z + a3.z;
        acc.w += a0.w + a1.w + a2.w + a3.w;
    }
    for (; k < cnt; k++) {
        float4 a = ((const float4*)(x + (size_t)g_cmembers[start + k] * CC))[t];
        acc.x += a.x; acc.y += a.y; acc.z += a.z; acc.w += a.w;
    }
    float inv = 1.0f / (float)(cnt > 0 ? cnt : 1);
    acc.x *= inv; acc.y *= inv; acc.z *= inv; acc.w *= inv;
    ((float4*)(out + OFF_XPOOL + (size_t)m * CC))[t] = acc;
    if (t < 32) {
        float ax = 0.f, ay = 0.f;
        for (int kk = t; kk < cnt; kk += 32) {
            int node = g_cmembers[start + kk];
            ax += xy[(size_t)node * 2];
            ay += xy[(size_t)node * 2 + 1];
        }
        for (int off = 16; off; off >>= 1) {
            ax += __shfl_xor_sync(0xffffffffu, ax, off);
            ay += __shfl_xor_sync(0xffffffffu, ay, off);
        }
        if (t == 0) {
            out[OFF_NEWXY + (size_t)m * 2]     = ax * inv;
            out[OFF_NEWXY + (size_t)m * 2 + 1] = ay * inv;
        }
    }
}

__global__ void edge_kernel(const int* __restrict__ ei, float* __restrict__ out) {
    for (int e = blockIdx.x * blockDim.x + threadIdx.x; e < EE; e += gridDim.x * blockDim.x) {
        int r = g_cluster[ei[e]];
        int c = g_cluster[ei[EE + e]];
        atomicAdd(&out[OFF_A + (size_t)r * MM + c], 1.0f);
    }
}

__global__ void tail_kernel(float* __restrict__ out) {
    for (int i = blockIdx.x * blockDim.x + threadIdx.x; i < NTOT; i += gridDim.x * blockDim.x) {
        out[OFF_CLUST + i] = (float)g_cluster[i];
        float fit;
        if (i == 0) fit = 0.f;
        else if (i <= NN1) fit = g_f1[i - 1];
        else fit = g_f2[i - 1 - NN1];
        out[OFF_FIT + i] = fit;
        if (i < MM) {
            out[OFF_BATCH + i] = 0.f;
            out[OFF_NNT + i] = (i == 0) ? 0.f : ((i <= KK1) ? 1.f : 2.f);
            out[OFF_NTREE + i] = (i == 0) ? -1.f : ((i <= KK1) ? 0.f : (float)((i - 1 - KK1) / 4 + 1));
            atomicAdd(&out[OFF_A + (size_t)i * MM + i], (float)g_countsM[i]);
        }
    }
}

// ---------------- launch ----------------
extern "C" void kernel_launch(void* const* d_in, const int* in_sizes, int n_in,
                              void* d_out, int out_size) {
    const float* x    = (const float*)d_in[0];
    const int*   ei   = (const int*)d_in[1];
    const int*   tree = (const int*)d_in[3];
    const float* xy   = (const float*)d_in[4];
    const float* w1   = (const float*)d_in[5];
    const float* w2   = (const float*)d_in[6];
    float* out = (float*)d_out;

    static cudaStream_t s1 = nullptr, s2 = nullptr;
    static cudaEvent_t e0 = nullptr, eMs = nullptr, eS1 = nullptr, eC2 = nullptr, eS1b = nullptr;
    if (!s1) {
        cudaStreamCreateWithFlags(&s1, cudaStreamNonBlocking);
        cudaStreamCreateWithFlags(&s2, cudaStreamNonBlocking);
        cudaEventCreateWithFlags(&e0, cudaEventDisableTiming);
        cudaEventCreateWithFlags(&eMs, cudaEventDisableTiming);
        cudaEventCreateWithFlags(&eS1, cudaEventDisableTiming);
        cudaEventCreateWithFlags(&eC2, cudaEventDisableTiming);
        cudaEventCreateWithFlags(&eS1b, cudaEventDisableTiming);
    }

    cudaEventRecord(e0, 0);
    cudaStreamWaitEvent(s1, e0, 0);
    cudaStreamWaitEvent(s2, e0, 0);

    // s2: A memset (needed only by edge/tail)
    cudaMemsetAsync(out + OFF_A, 0, (size_t)MM * MM * sizeof(float), s2);
    cudaEventRecord(eMs, s2);

    // s1: f1-dependent chain, hidden under f2's bandwidth sweep
    f1_kernel<<<1024, 256, 0, s1>>>(x, w1, tree);
    rank_kernel<<<256, 256, 0, s1>>>();
    thr_kernel<<<32, 256, 0, s1>>>(xy);
    cluster1_kernel<<<NN1 / 8, 256, 0, s1>>>(xy);
    parents_kernel<<<NN2 / 256, 256, 0, s1>>>(tree);
    scan_kernel<<<1, 256, 0, s1>>>(0);
    scatter1_kernel<<<NN2 / 256, 256, 0, s1>>>();
    cudaEventRecord(eS1, s1);

    // s0: the big f2 sweep
    f2_kernel<<<NN2 * 32 / 256, 256>>>(x, w2);

    // join: top4 needs f2 + scatter1
    cudaStreamWaitEvent(0, eS1, 0);
    top4_kernel<<<(KK1 * 32 + 255) / 256, 256>>>(xy);
    cluster2_kernel<<<NN2 / 256, 256>>>(xy);
    cudaEventRecord(eC2, 0);

    // s1: edge + tail (need cluster complete + memset), concurrent with pool
    cudaStreamWaitEvent(s1, eC2, 0);
    cudaStreamWaitEvent(s1, eMs, 0);
    edge_kernel<<<2048, 256, 0, s1>>>(ei, out);
    tail_kernel<<<(NTOT + 255) / 256, 256, 0, s1>>>(out);
    cudaEventRecord(eS1b, s1);

    // s0: scanM -> scatterM -> pool
    scan_kernel<<<1, 256>>>(1);
    scatterM_kernel<<<(NTOT + 255) / 256, 256>>>();
    pool_kernel<<<MM, 128>>>(x, xy, out);
    cudaStreamWaitEvent(0, eS1b, 0);
}